// round 15
// baseline (speedup 1.0000x reference)
#include <cuda_runtime.h>
#include <cuda_bf16.h>
#include <math.h>
#include <stdint.h>

// Problem constants
#define NB   32
#define CIN  64
#define COUT 128
#define TT   256
#define VV   25
#define IC   32
#define SLEN (TT*VV)          // 6400 flattened (t,v)
#define EPS  1e-5f
#define STILE 128
#define STILE2 256
#define NSTILE2 (SLEN/STILE2) // 25

#if defined(__CUDA_ARCH__) && (defined(__CUDA_ARCH_FEAT_SM103_ALL) || defined(__CUDA_ARCH_FEAT_SM100_ALL))
#define HAS_TC 1
#else
#define HAS_TC 0
#endif

// ---------------------------------------------------------------------------
// Device scratch (no allocation allowed). 16B-aligned for uint4 access.
// ---------------------------------------------------------------------------
__device__ __align__(16) __nv_bfloat16 g_zhi[(size_t)NB*SLEN*COUT];   // z^T [n][s][o]
__device__ __align__(16) __nv_bfloat16 g_zlo[(size_t)NB*SLEN*COUT];
__device__ __align__(16) __nv_bfloat16 g_xthi[(size_t)NB*SLEN*CIN];  // x^T [n][s][c]
__device__ __align__(16) __nv_bfloat16 g_xtlo[(size_t)NB*SLEN*CIN];
__device__ __align__(16) __nv_bfloat16 g_x3hi[(size_t)NB*SLEN*COUT]; // w3@x [n][s][o]
__device__ __align__(16) __nv_bfloat16 g_x3lo[(size_t)NB*SLEN*COUT];
__device__ __align__(16) __nv_bfloat16 g_x4hi[(size_t)NB*SLEN*COUT]; // w4@x [n][s][o]
__device__ __align__(16) __nv_bfloat16 g_x4lo[(size_t)NB*SLEN*COUT];
__device__ __align__(16) __nv_bfloat16 g_whi[9*COUT*COUT];            // wt [k][o][i]
__device__ __align__(16) __nv_bfloat16 g_wlo[9*COUT*COUT];
__device__ __align__(16) __nv_bfloat16 g_wrhi[COUT*CIN];              // wr [o][c]
__device__ __align__(16) __nv_bfloat16 g_wrlo[COUT*CIN];
__device__ __align__(16) __nv_bfloat16 g_w3hi[COUT*CIN];              // w3 [o][c]
__device__ __align__(16) __nv_bfloat16 g_w3lo[COUT*CIN];
__device__ __align__(16) __nv_bfloat16 g_w4hi[COUT*CIN];              // w4 [o][c]
__device__ __align__(16) __nv_bfloat16 g_w4lo[COUT*CIN];
__device__ __align__(16) float g_s[NB*IC*VV];                         // softmax weights
__device__ __align__(16) float g_xbar[NB*CIN*VV];                     // T-mean accum

// ---------------------------------------------------------------------------
// PTX helpers
// ---------------------------------------------------------------------------
__device__ __forceinline__ uint32_t smem_u32(const void* p) {
    uint32_t a;
    asm("{ .reg .u64 t; cvta.to.shared.u64 t, %1; cvt.u32.u64 %0, t; }"
        : "=r"(a) : "l"(p));
    return a;
}

#if HAS_TC
__device__ __forceinline__ uint32_t elect_one_pred() {
    uint32_t pred;
    asm volatile("{\n\t.reg .pred p;\n\telect.sync _|p, 0xFFFFFFFF;\n\t"
                 "selp.b32 %0, 1, 0, p;\n\t}" : "=r"(pred));
    return pred;
}
#define TCGEN05_ALLOC(smem_addr, nCols) \
    asm volatile("tcgen05.alloc.cta_group::1.sync.aligned.shared::cta.b32 [%0], %1;" \
        :: "r"((uint32_t)(smem_addr)), "r"((uint32_t)(nCols)) : "memory")
#define TCGEN05_DEALLOC(tmem_addr, nCols) \
    asm volatile("tcgen05.dealloc.cta_group::1.sync.aligned.b32 %0, %1;" \
        :: "r"(tmem_addr), "r"((uint32_t)(nCols)))
#define TCGEN05_COMMIT(mbar) \
    asm volatile("tcgen05.commit.cta_group::1.mbarrier::arrive::one.shared::cluster.b64 [%0];" \
        :: "r"((uint32_t)(mbar)) : "memory")
#define TCGEN05_FENCE_AFTER() \
    asm volatile("tcgen05.fence::after_thread_sync;" ::: "memory")
#define TCGEN05_FENCE_BEFORE() \
    asm volatile("tcgen05.fence::before_thread_sync;" ::: "memory")
#define TCGEN05_WAIT_LD() \
    asm volatile("tcgen05.wait::ld.sync.aligned;" ::: "memory")
#define FENCE_PROXY_ASYNC() \
    asm volatile("fence.proxy.async.shared::cta;" ::: "memory")
#define MBARRIER_INIT(mbar, cnt) \
    asm volatile("mbarrier.init.shared.b64 [%0], %1;" \
        :: "r"((uint32_t)(mbar)), "r"((uint32_t)(cnt)) : "memory")
#define MBARRIER_INVAL(mbar) \
    asm volatile("mbarrier.inval.shared.b64 [%0];" :: "r"((uint32_t)(mbar)) : "memory")
#define MBARRIER_WAIT_PARITY(mbar, phase) do { \
    uint32_t _m = (uint32_t)(mbar); uint32_t _p = (uint32_t)(phase); uint32_t _d; \
    asm volatile("{\n\t.reg .pred p;\n\t" \
        "mbarrier.try_wait.parity.acquire.cta.shared::cta.b64 p, [%1], %2;\n\t" \
        "selp.b32 %0, 1, 0, p;\n\t}" : "=r"(_d) : "r"(_m), "r"(_p) : "memory"); \
    if (!_d) { \
        asm volatile("{\n\t.reg .pred P1;\n\t" \
            "WAIT_LOOP_%=:\n\t" \
            "mbarrier.try_wait.parity.acquire.cta.shared::cta.b64 P1, [%0], %1, 0x989680;\n\t" \
            "@P1 bra.uni WAIT_DONE_%=;\n\t" \
            "bra.uni WAIT_LOOP_%=;\n\t" \
            "WAIT_DONE_%=:\n\t}" :: "r"(_m), "r"(_p) : "memory"); \
    } \
} while (0)
#define TCGEN05_LD_32X32B_X32(r, tmem_addr) \
    asm volatile("tcgen05.ld.sync.aligned.32x32b.x32.b32 " \
        "{%0, %1, %2, %3, %4, %5, %6, %7, " \
        " %8, %9, %10, %11, %12, %13, %14, %15, " \
        " %16, %17, %18, %19, %20, %21, %22, %23, " \
        " %24, %25, %26, %27, %28, %29, %30, %31}, [%32];" \
        : "=r"((r)[0]),  "=r"((r)[1]),  "=r"((r)[2]),  "=r"((r)[3]), \
          "=r"((r)[4]),  "=r"((r)[5]),  "=r"((r)[6]),  "=r"((r)[7]), \
          "=r"((r)[8]),  "=r"((r)[9]),  "=r"((r)[10]), "=r"((r)[11]), \
          "=r"((r)[12]), "=r"((r)[13]), "=r"((r)[14]), "=r"((r)[15]), \
          "=r"((r)[16]), "=r"((r)[17]), "=r"((r)[18]), "=r"((r)[19]), \
          "=r"((r)[20]), "=r"((r)[21]), "=r"((r)[22]), "=r"((r)[23]), \
          "=r"((r)[24]), "=r"((r)[25]), "=r"((r)[26]), "=r"((r)[27]), \
          "=r"((r)[28]), "=r"((r)[29]), "=r"((r)[30]), "=r"((r)[31]) \
        : "r"(tmem_addr))

static constexpr uint64_t DESC_BASE_SW128 =
    (uint64_t(2) << 61) | (uint64_t(1) << 46) | (uint64_t(64) << 32) | (uint64_t(1) << 16);
__device__ __forceinline__ uint64_t make_desc(uint32_t addr) {
    return DESC_BASE_SW128 | ((uint64_t)(addr >> 4) & 0x3FFF);
}
#define MMA_IDESC 0x8200490u

__device__ __forceinline__ void mma_f16_ss(uint32_t d, uint64_t ad, uint64_t bd,
                                           uint32_t idesc, bool en) {
    uint32_t e = en ? 1u : 0u, z = 0u;
    asm volatile("{\n\t.reg .pred p;\n\tsetp.ne.u32 p, %5, 0;\n\t"
        "tcgen05.mma.cta_group::1.kind::f16 [%0], %1, %2, %3, {%4, %4, %4, %4}, p;\n\t}"
        :: "r"(d), "l"(ad), "l"(bd), "r"(idesc), "r"(z), "r"(e) : "memory");
}
#endif  // HAS_TC

#define SWZ128(x) ((x) ^ (((x) >> 3) & 0x70))

// ---------------------------------------------------------------------------
// Prep kernels: weight bf16 hi/lo splits
// ---------------------------------------------------------------------------
__global__ void kernelW(const float* __restrict__ wt)
{
    int idx = blockIdx.x * 256 + threadIdx.x;
    if (idx >= 9*COUT*COUT) return;
    int k = idx / (COUT*COUT);
    int r = idx % (COUT*COUT);
    int o = r / COUT, i = r % COUT;
    float w = wt[((size_t)o*COUT + i)*9 + k];
    __nv_bfloat16 h = __float2bfloat16(w);
    g_whi[idx] = h;
    g_wlo[idx] = __float2bfloat16(w - __bfloat162float(h));
}

__global__ void kernelW2(const float* __restrict__ wr,
                         const float* __restrict__ w3,
                         const float* __restrict__ w4)
{
    int idx = blockIdx.x * 256 + threadIdx.x;
    if (idx >= COUT*CIN) return;
    float w = wr[idx];
    __nv_bfloat16 h = __float2bfloat16(w);
    g_wrhi[idx] = h; g_wrlo[idx] = __float2bfloat16(w - __bfloat162float(h));
    w = w3[idx]; h = __float2bfloat16(w);
    g_w3hi[idx] = h; g_w3lo[idx] = __float2bfloat16(w - __bfloat162float(h));
    w = w4[idx]; h = __float2bfloat16(w);
    g_w4hi[idx] = h; g_w4lo[idx] = __float2bfloat16(w - __bfloat162float(h));
}

// ---------------------------------------------------------------------------
// Kernel BX: transpose x -> xT[n][s][c] bf16 hi/lo
// ---------------------------------------------------------------------------
__global__ void __launch_bounds__(256) kernelBX(const float* __restrict__ x)
{
    __shared__ float xs[CIN*101];
    const int n  = blockIdx.y;
    const int s0 = blockIdx.x * 100;
    const int tid = threadIdx.x;

    for (int idx = tid; idx < CIN*100; idx += 256) {
        const int c = idx / 100, j = idx % 100;
        xs[c*101 + j] = x[((size_t)(n*CIN + c))*SLEN + s0 + j];
    }
    __syncthreads();
    for (int idx = tid; idx < CIN*100; idx += 256) {
        const int j = idx / CIN, c = idx % CIN;
        const float v = xs[c*101 + j];
        const __nv_bfloat16 h = __float2bfloat16(v);
        const size_t base = ((size_t)(n*SLEN + s0 + j))*CIN + c;
        g_xthi[base] = h;
        g_xtlo[base] = __float2bfloat16(v - __bfloat162float(h));
    }
}

// ---------------------------------------------------------------------------
// Kernel A split: A0 zero, A1 partial T-mean via atomicAdd, A2 softmax
// ---------------------------------------------------------------------------
__global__ void kernelA0()
{
    int idx = blockIdx.x * 256 + threadIdx.x;
    if (idx < NB*CIN*VV) g_xbar[idx] = 0.f;
}

__global__ void kernelA1(const float* __restrict__ x)
{
    const int n = blockIdx.y;
    const int tbase = blockIdx.x * (TT/8);
    const int tid = threadIdx.x;
    for (int idx = tid; idx < CIN*VV; idx += 256) {
        int c = idx / VV, v = idx % VV;
        const float* xp = x + (((size_t)(n*CIN + c)*TT) + tbase)*VV + v;
        float sum = 0.f;
        #pragma unroll 8
        for (int t = 0; t < TT/8; ++t) sum += xp[t*VV];
        atomicAdd(&g_xbar[n*CIN*VV + idx], sum * (1.0f/256.0f));
    }
}

__global__ void kernelA2(const float* __restrict__ w2,
                         const float* __restrict__ b2)
{
    const int n = blockIdx.x;
    const int tid = threadIdx.x;
    __shared__ float xbar[CIN*VV];
    __shared__ float x2s[IC*VV];

    for (int idx = tid; idx < CIN*VV; idx += 256)
        xbar[idx] = g_xbar[n*CIN*VV + idx];
    __syncthreads();
    for (int idx = tid; idx < IC*VV; idx += 256) {
        int i = idx / VV, v = idx % VV;
        float acc = b2[i];
        for (int c = 0; c < CIN; ++c)
            acc = fmaf(w2[i*CIN + c], xbar[c*VV + v], acc);
        x2s[idx] = acc;
    }
    __syncthreads();
    if (tid < IC) {
        const int i = tid;
        float mx = -1e30f;
        #pragma unroll
        for (int v = 0; v < VV; ++v) mx = fmaxf(mx, -x2s[i*VV + v]);
        float e[VV]; float sum = 0.f;
        #pragma unroll
        for (int v = 0; v < VV; ++v) { e[v] = expf(-x2s[i*VV + v] - mx); sum += e[v]; }
        float inv = 1.0f / sum;
        #pragma unroll
        for (int v = 0; v < VV; ++v) g_s[(n*IC + i)*VV + v] = e[v] * inv;
    }
}

// ---------------------------------------------------------------------------
// Kernel P v2: dual s-tile per block. W3/W4 loaded once; X(tile1) register-
// prefetched during tile0 MMA; tile0 epilogue overlaps tile1 MMA (separate D).
// ---------------------------------------------------------------------------
#define P_TMEM   0
#define P_MBAR   8
#define P_X_HI   1024
#define P_X_LO   (P_X_HI + 16384)
#define P_W3_HI  (P_X_LO + 16384)
#define P_W3_LO  (P_W3_HI + 16384)
#define P_W4_HI  (P_W3_LO + 16384)
#define P_W4_LO  (P_W4_HI + 16384)
#define SMEM_P_TOTAL (P_W4_LO + 16384)   // 99328

__global__ void __launch_bounds__(256) kernelP()
{
    extern __shared__ char smem[];
    const int n  = blockIdx.y;
    const int s0 = blockIdx.x * STILE2;   // two 128-tiles: s0, s0+128
    const int tid = threadIdx.x;

#if HAS_TC
    const uint32_t sb = smem_u32(smem);
    const int wid = tid >> 5;
    const int lane = tid & 31;

    if (wid == 0) { TCGEN05_ALLOC(sb + P_TMEM, 512); }
    if (tid == 0) MBARRIER_INIT(sb + P_MBAR, 1);
    __syncthreads();
    uint32_t tmem;
    asm volatile("ld.shared.b32 %0, [%1];" : "=r"(tmem) : "r"(sb + P_TMEM));

    // Loads: X tile0 + W3/W4 (once)
    for (int idx = tid; idx < 1024; idx += 256) {
        const int row = idx >> 3, c8 = idx & 7;
        const uint32_t so = SWZ128((row << 7) + (c8 << 4));
        const size_t xb = ((size_t)(n*SLEN) + s0 + row)*CIN;
        *(uint4*)(smem + P_X_HI + so)  = *((const uint4*)(g_xthi + xb) + c8);
        *(uint4*)(smem + P_X_LO + so)  = *((const uint4*)(g_xtlo + xb) + c8);
        *(uint4*)(smem + P_W3_HI + so) = *((const uint4*)(g_w3hi + (size_t)row*CIN) + c8);
        *(uint4*)(smem + P_W3_LO + so) = *((const uint4*)(g_w3lo + (size_t)row*CIN) + c8);
        *(uint4*)(smem + P_W4_HI + so) = *((const uint4*)(g_w4hi + (size_t)row*CIN) + c8);
        *(uint4*)(smem + P_W4_LO + so) = *((const uint4*)(g_w4lo + (size_t)row*CIN) + c8);
    }
    FENCE_PROXY_ASYNC();
    __syncthreads();

    // MMA tile0 -> D at 0 (x3) / 128 (x4)
    if (wid == 0) {
        TCGEN05_FENCE_AFTER();
        if (elect_one_pred()) {
            const uint32_t XO[3] = { P_X_HI, P_X_LO, P_X_HI };
            #pragma unroll
            for (int dsel = 0; dsel < 2; ++dsel) {
                const uint32_t WH = dsel ? P_W4_HI : P_W3_HI;
                const uint32_t WL = dsel ? P_W4_LO : P_W3_LO;
                const uint32_t WO[3] = { WH, WH, WL };
                const uint32_t d = tmem + dsel*128;
                #pragma unroll
                for (int c3 = 0; c3 < 3; ++c3) {
                    uint64_t ad = make_desc(sb + XO[c3]);
                    uint64_t bd = make_desc(sb + WO[c3]);
                    #pragma unroll
                    for (int ks = 0; ks < 4; ++ks) {
                        const bool en = !(c3 == 0 && ks == 0);
                        mma_f16_ss(d, ad + ks*2, bd + ks*2, MMA_IDESC, en);
                    }
                }
            }
            TCGEN05_COMMIT(sb + P_MBAR);
        }
    }

    // prefetch X tile1 into regs (overlaps MMA0)
    uint4 pxh[4], pxl[4];
    #pragma unroll
    for (int j = 0; j < 4; ++j) {
        const int idx = tid + 256*j;
        const int row = idx >> 3, c8 = idx & 7;
        const size_t xb = ((size_t)(n*SLEN) + s0 + 128 + row)*CIN;
        pxh[j] = *((const uint4*)(g_xthi + xb) + c8);
        pxl[j] = *((const uint4*)(g_xtlo + xb) + c8);
    }

    MBARRIER_WAIT_PARITY(sb + P_MBAR, 0);   // tile0 MMA done

    // store X tile1
    #pragma unroll
    for (int j = 0; j < 4; ++j) {
        const int idx = tid + 256*j;
        const int row = idx >> 3, c8 = idx & 7;
        const uint32_t so = SWZ128((row << 7) + (c8 << 4));
        *(uint4*)(smem + P_X_HI + so) = pxh[j];
        *(uint4*)(smem + P_X_LO + so) = pxl[j];
    }
    FENCE_PROXY_ASYNC();
    __syncthreads();

    // MMA tile1 -> D at 256 (x3) / 384 (x4)
    if (wid == 0) {
        TCGEN05_FENCE_AFTER();
        if (elect_one_pred()) {
            const uint32_t XO[3] = { P_X_HI, P_X_LO, P_X_HI };
            #pragma unroll
            for (int dsel = 0; dsel < 2; ++dsel) {
                const uint32_t WH = dsel ? P_W4_HI : P_W3_HI;
                const uint32_t WL = dsel ? P_W4_LO : P_W3_LO;
                const uint32_t WO[3] = { WH, WH, WL };
                const uint32_t d = tmem + 256 + dsel*128;
                #pragma unroll
                for (int c3 = 0; c3 < 3; ++c3) {
                    uint64_t ad = make_desc(sb + XO[c3]);
                    uint64_t bd = make_desc(sb + WO[c3]);
                    #pragma unroll
                    for (int ks = 0; ks < 4; ++ks) {
                        const bool en = !(c3 == 0 && ks == 0);
                        mma_f16_ss(d, ad + ks*2, bd + ks*2, MMA_IDESC, en);
                    }
                }
            }
            TCGEN05_COMMIT(sb + P_MBAR);
        }
    }

    // epilogue tile0 (D0 complete; overlaps tile1 MMA)
    TCGEN05_FENCE_AFTER();
    if (wid < 4) {
        const int srow = s0 + wid * 32 + lane;
        const size_t base = ((size_t)(n*SLEN) + srow)*COUT;
        #pragma unroll
        for (int cb = 0; cb < 128; cb += 32) {
            uint32_t r1[32], r2[32];
            TCGEN05_LD_32X32B_X32(r1, tmem + cb);
            TCGEN05_LD_32X32B_X32(r2, tmem + 128 + cb);
            TCGEN05_WAIT_LD();
            #pragma unroll
            for (int j = 0; j < 32; ++j) {
                const int o = cb + j;
                float v3 = __uint_as_float(r1[j]);
                __nv_bfloat16 h3 = __float2bfloat16(v3);
                g_x3hi[base + o] = h3;
                g_x3lo[base + o] = __float2bfloat16(v3 - __bfloat162float(h3));
                float v4 = __uint_as_float(r2[j]);
                __nv_bfloat16 h4 = __float2bfloat16(v4);
                g_x4hi[base + o] = h4;
                g_x4lo[base + o] = __float2bfloat16(v4 - __bfloat162float(h4));
            }
        }
        TCGEN05_FENCE_BEFORE();
    }

    MBARRIER_WAIT_PARITY(sb + P_MBAR, 1);   // tile1 MMA done
    TCGEN05_FENCE_AFTER();
    if (wid >= 4) {
        const int srow = s0 + 128 + (wid - 4) * 32 + lane;
        const size_t base = ((size_t)(n*SLEN) + srow)*COUT;
        #pragma unroll
        for (int cb = 0; cb < 128; cb += 32) {
            uint32_t r1[32], r2[32];
            TCGEN05_LD_32X32B_X32(r1, tmem + 256 + cb);
            TCGEN05_LD_32X32B_X32(r2, tmem + 384 + cb);
            TCGEN05_WAIT_LD();
            #pragma unroll
            for (int j = 0; j < 32; ++j) {
                const int o = cb + j;
                float v3 = __uint_as_float(r1[j]);
                __nv_bfloat16 h3 = __float2bfloat16(v3);
                g_x3hi[base + o] = h3;
                g_x3lo[base + o] = __float2bfloat16(v3 - __bfloat162float(h3));
                float v4 = __uint_as_float(r2[j]);
                __nv_bfloat16 h4 = __float2bfloat16(v4);
                g_x4hi[base + o] = h4;
                g_x4lo[base + o] = __float2bfloat16(v4 - __bfloat162float(h4));
            }
        }
        TCGEN05_FENCE_BEFORE();
    }

    __syncthreads();
    if (tid == 0) MBARRIER_INVAL(sb + P_MBAR);
    __syncthreads();
    if (wid == 0) TCGEN05_DEALLOC(tmem, 512);
#else
    // FFMA fallback: two tiles sequentially
    __syncthreads();
    const int tx = tid & 15, ty = tid >> 4;
    float* Xs = (float*)(smem + P_X_HI);
    float* Ws = (float*)(smem + P_X_HI + 16896);
    for (int half = 0; half < 2; ++half) {
        const int s0h = s0 + half*128;
        for (int dsel = 0; dsel < 2; ++dsel) {
            float acc[8][8];
            #pragma unroll
            for (int r = 0; r < 8; ++r)
                #pragma unroll
                for (int j = 0; j < 8; ++j) acc[r][j] = 0.f;
            for (int ic = 0; ic < 2; ++ic) {
                __syncthreads();
                for (int idx = tid; idx < 4096; idx += 256) {
                    const int row = idx >> 5, i = idx & 31;
                    const int gi = ic*32 + i;
                    const size_t xb = ((size_t)(n*SLEN) + s0h + row)*CIN + gi;
                    Xs[i*132 + row] = __bfloat162float(g_xthi[xb]) + __bfloat162float(g_xtlo[xb]);
                    const __nv_bfloat16* whp = dsel ? g_w4hi : g_w3hi;
                    const __nv_bfloat16* wlp = dsel ? g_w4lo : g_w3lo;
                    Ws[i*132 + row] = __bfloat162float(whp[row*CIN + gi])
                                    + __bfloat162float(wlp[row*CIN + gi]);
                }
                __syncthreads();
                for (int i = 0; i < 32; ++i) {
                    float zr[8], wv[8];
                    #pragma unroll
                    for (int j = 0; j < 8; ++j) zr[j] = Xs[i*132 + tx*8 + j];
                    #pragma unroll
                    for (int r = 0; r < 8; ++r) wv[r] = Ws[i*132 + ty*8 + r];
                    #pragma unroll
                    for (int r = 0; r < 8; ++r)
                        #pragma unroll
                        for (int j = 0; j < 8; ++j)
                            acc[r][j] = fmaf(wv[r], zr[j], acc[r][j]);
                }
            }
            __nv_bfloat16* dh = dsel ? g_x4hi : g_x3hi;
            __nv_bfloat16* dl = dsel ? g_x4lo : g_x3lo;
            #pragma unroll
            for (int r = 0; r < 8; ++r) {
                const int o = ty*8 + r;
                #pragma unroll
                for (int j = 0; j < 8; ++j) {
                    const int srow = s0h + tx*8 + j;
                    const size_t base = ((size_t)(n*SLEN) + srow)*COUT + o;
                    float v = acc[r][j];
                    __nv_bfloat16 h = __float2bfloat16(v);
                    dh[base] = h;
                    dl[base] = __float2bfloat16(v - __bfloat162float(h));
                }
            }
            __syncthreads();
        }
    }
#endif
}

// ---------------------------------------------------------------------------
// Kernel Z: z = relu(bn1(g + A@(x4+b4))) from x3T/x4T. grid (TT, NB), 128 thr.
// ---------------------------------------------------------------------------
__global__ void __launch_bounds__(128) kernelZ(
    const float* __restrict__ Amat,
    const float* __restrict__ b3, const float* __restrict__ b4,
    const float* __restrict__ bn1_g, const float* __restrict__ bn1_b,
    const float* __restrict__ bn1_m, const float* __restrict__ bn1_v)
{
    const int n = blockIdx.y;
    const int t = blockIdx.x;
    const int o = threadIdx.x;
    const int c32 = o & 31;

    __shared__ float As[VV*VV];
    __shared__ float ss[IC*VV];
    for (int idx = o; idx < VV*VV; idx += 128) As[idx] = Amat[idx];
    for (int idx = o; idx < IC*VV; idx += 128) ss[idx] = g_s[n*IC*VV + idx];
    __syncthreads();

    const float scale1 = bn1_g[o] * rsqrtf(bn1_v[o] + EPS);
    const float shift1 = bn1_b[o] - bn1_m[o] * scale1;
    const float b3o = b3[o], b4o = b4[o];

    const size_t base = ((size_t)(n*SLEN) + t*VV)*COUT + o;
    float x3v[VV], x4v[VV];
    #pragma unroll
    for (int v = 0; v < VV; ++v) {
        const size_t a = base + (size_t)v*COUT;
        x3v[v] = __bfloat162float(g_x3hi[a]) + __bfloat162float(g_x3lo[a]);
        x4v[v] = __bfloat162float(g_x4hi[a]) + __bfloat162float(g_x4lo[a]) + b4o;
    }

    float g = b3o;
    const float* srow = &ss[c32*VV];
    #pragma unroll
    for (int v = 0; v < VV; ++v) g = fmaf(srow[v], x3v[v], g);

    #pragma unroll
    for (int u = 0; u < VV; ++u) {
        float y2 = 0.f;
        const float* arow = &As[u*VV];
        #pragma unroll
        for (int v = 0; v < VV; ++v) y2 = fmaf(arow[v], x4v[v], y2);
        float z = fmaxf(fmaf(scale1, g + y2, shift1), 0.f);
        __nv_bfloat16 zh = __float2bfloat16(z);
        const size_t a = base + (size_t)u*COUT;
        g_zhi[a] = zh;
        g_zlo[a] = __float2bfloat16(z - __bfloat162float(zh));
    }
}

// ---------------------------------------------------------------------------
// Kernel C v4: dual s-tile, register-prefetched A halo AND B_hi tap weights.
// ---------------------------------------------------------------------------
#define SM_TMEM   0
#define SM_MBAR   8
#define SM_SC2    16
#define SM_SCR    528
#define SM_SHT    1040
#define SM_A      2048                   // hi: p0@0 p1@32768 ; lo: +65536
#define SM_B      (SM_A + 131072)        // hi p0@0 p1@16384 ; lo +32768
#define SMEM_C_TOTAL (SM_B + 65536)      // 198656

__global__ void __launch_bounds__(256) kernelC(
    const float* __restrict__ bt,
    const float* __restrict__ bn2_g, const float* __restrict__ bn2_b,
    const float* __restrict__ bn2_m, const float* __restrict__ bn2_v,
    const float* __restrict__ br,
    const float* __restrict__ bnr_g, const float* __restrict__ bnr_b,
    const float* __restrict__ bnr_m, const float* __restrict__ bnr_v,
    float* __restrict__ out)
{
    extern __shared__ char smem[];
    const int n  = blockIdx.y;
    const int s0 = blockIdx.x * STILE2;
    const int tid = threadIdx.x;

    if (tid < COUT) {
        float sc2 = bn2_g[tid] * rsqrtf(bn2_v[tid] + EPS);
        float sh2 = bn2_b[tid] - bn2_m[tid] * sc2;
        float scr = bnr_g[tid] * rsqrtf(bnr_v[tid] + EPS);
        float shr = bnr_b[tid] - bnr_m[tid] * scr;
        ((float*)(smem + SM_SC2))[tid] = sc2;
        ((float*)(smem + SM_SCR))[tid] = scr;
        ((float*)(smem + SM_SHT))[tid] = fmaf(sc2, bt[tid], sh2) + fmaf(scr, br[tid], shr);
    }

    const __nv_bfloat16* zh = g_zhi + (size_t)n * SLEN * COUT;
    const __nv_bfloat16* zl = g_zlo + (size_t)n * SLEN * COUT;

#if HAS_TC
    const uint32_t sb = smem_u32(smem);
    const int wid = tid >> 5;
    const int lane = tid & 31;

    if (wid == 0) { TCGEN05_ALLOC(sb + SM_TMEM, 512); }
    if (tid == 0) MBARRIER_INIT(sb + SM_MBAR, 1);
    __syncthreads();
    uint32_t tmem;
    asm volatile("ld.shared.b32 %0, [%1];" : "=r"(tmem) : "r"(sb + SM_TMEM));

    // ---- stage 0: res GEMM ----
    for (int idx = tid; idx < 2048; idx += 256) {
        const int row = idx >> 3, c8 = idx & 7;
        const uint32_t so = SWZ128((row << 7) + (c8 << 4));
        const size_t xb = ((size_t)(n*SLEN) + s0 + row)*CIN;
        *(uint4*)(smem + SM_A + so)          = *((const uint4*)(g_xthi + xb) + c8);
        *(uint4*)(smem + SM_A + 65536 + so)  = *((const uint4*)(g_xtlo + xb) + c8);
    }
    for (int idx = tid; idx < 1024; idx += 256) {
        const int row = idx >> 3, c8 = idx & 7;
        const uint32_t so = SWZ128((row << 7) + (c8 << 4));
        *(uint4*)(smem + SM_B + so)         = *((const uint4*)(g_wrhi + (size_t)row*CIN) + c8);
        *(uint4*)(smem + SM_B + 32768 + so) = *((const uint4*)(g_wrlo + (size_t)row*CIN) + c8);
    }
    FENCE_PROXY_ASYNC();
    __syncthreads();

    if (wid == 0) {
        TCGEN05_FENCE_AFTER();
        if (elect_one_pred()) {
            #pragma unroll
            for (int tile = 0; tile < 2; ++tile) {
                const uint32_t d = tmem + 256 + tile*128;
                const uint32_t XO[3] = { 0u, 65536u, 0u };
                const uint32_t WO[3] = { 0u, 0u, 32768u };
                #pragma unroll
                for (int c3 = 0; c3 < 3; ++c3) {
                    uint64_t ad = make_desc(sb + SM_A + XO[c3] + tile*16384);
                    uint64_t bd = make_desc(sb + SM_B + WO[c3]);
                    #pragma unroll
                    for (int ks = 0; ks < 4; ++ks) {
                        const bool en = !(c3 == 0 && ks == 0);
                        mma_f16_ss(d, ad + ks*2, bd + ks*2, MMA_IDESC, en);
                    }
                }
            }
            TCGEN05_COMMIT(sb + SM_MBAR);
        }
    }

    // ---- prefetch A halo (tap 0) + B_hi (tap 0) into registers ----
    uint4 pah[16], pal[16], pbh[8];
    {
        const int sbase = s0 - 100;
        #pragma unroll
        for (int j = 0; j < 16; ++j) {
            const int idx = tid + 256*j;
            const int row = idx >> 4, c = idx & 15;
            const int sg = sbase + row;
            uint4 vh = make_uint4(0,0,0,0), vl = make_uint4(0,0,0,0);
            if ((unsigned)sg < (unsigned)SLEN) {
                vh = *((const uint4*)(zh + (size_t)sg * COUT) + c);
                vl = *((const uint4*)(zl + (size_t)sg * COUT) + c);
            }
            pah[j] = vh; pal[j] = vl;
        }
        const uint4* wh = (const uint4*)(g_whi);
        #pragma unroll
        for (int j = 0; j < 8; ++j) pbh[j] = wh[tid + 256*j];
    }

    // ---- conv stages ----
    for (int st = 1; st <= 9; ++st) {
        const int k = st - 1;
        MBARRIER_WAIT_PARITY(sb + SM_MBAR, (st - 1) & 1);

        // store prefetched A halo + B_hi
        #pragma unroll
        for (int j = 0; j < 16; ++j) {
            const int idx = tid + 256*j;
            const int row = idx >> 4, c = idx & 15;
            const uint32_t so = ((c >> 3) << 15) + SWZ128((row << 7) + ((c & 7) << 4));
            *(uint4*)(smem + SM_A + so)         = pah[j];
            *(uint4*)(smem + SM_A + 65536 + so) = pal[j];
        }
        #pragma unroll
        for (int j = 0; j < 8; ++j) {
            const int idx = tid + 256*j;
            const int row = idx >> 4, c = idx & 15;
            const uint32_t so = ((c >> 3) << 14) + SWZ128((row << 7) + ((c & 7) << 4));
            *(uint4*)(smem + SM_B + so) = pbh[j];
        }
        // B_lo direct
        const uint4* wl = (const uint4*)(g_wlo + (size_t)k * COUT * COUT);
        for (int idx = tid; idx < 2048; idx += 256) {
            const int row = idx >> 4, c = idx & 15;
            const uint32_t so = ((c >> 3) << 14) + SWZ128((row << 7) + ((c & 7) << 4));
            *(uint4*)(smem + SM_B + 32768 + so) = wl[idx];
        }
        FENCE_PROXY_ASYNC();
        __syncthreads();

        if (wid == 0) {
            TCGEN05_FENCE_AFTER();
            if (elect_one_pred()) {
                const uint32_t ALO[3] = { 0u, 65536u, 0u };
                const uint32_t BLO[3] = { 0u, 0u, 32768u };
                #pragma unroll
                for (int tile = 0; tile < 2; ++tile) {
                    const uint32_t d = tmem + tile*128;
                    #pragma unroll
                    for (int c3 = 0; c3 < 3; ++c3) {
                        #pragma unroll
                        for (int pl = 0; pl < 2; ++pl) {
                            uint64_t ad = make_desc(sb + SM_A + ALO[c3] + (pl << 15) + tile*16384);
                            uint64_t bd = make_desc(sb + SM_B + BLO[c3] + (pl << 14));
                            #pragma unroll
                            for (int ks = 0; ks < 4; ++ks) {
                                const bool en = !(st == 1 && c3 == 0 && pl == 0 && ks == 0);
                                mma_f16_ss(d, ad + ks*2, bd + ks*2, MMA_IDESC, en);
                            }
                        }
                    }
                }
                TCGEN05_COMMIT(sb + SM_MBAR);
            }
        }

        // prefetch next tap's A halo + B_hi (gmem reads only; overlap MMA)
        if (st < 9) {
            const int sbase = s0 + 25*st - 100;
            #pragma unroll
            for (int j = 0; j < 16; ++j) {
                const int idx = tid + 256*j;
                const int row = idx >> 4, c = idx & 15;
                const int sg = sbase + row;
                uint4 vh = make_uint4(0,0,0,0), vl = make_uint4(0,0,0,0);
                if ((unsigned)sg < (unsigned)SLEN) {
                    vh = *((const uint4*)(zh + (size_t)sg * COUT) + c);
                    vl = *((const uint4*)(zl + (size_t)sg * COUT) + c);
                }
                pah[j] = vh; pal[j] = vl;
            }
            const uint4* wh = (const uint4*)(g_whi + (size_t)st * COUT * COUT);
            #pragma unroll
            for (int j = 0; j < 8; ++j) pbh[j] = wh[tid + 256*j];
        }
    }

    MBARRIER_WAIT_PARITY(sb + SM_MBAR, 1);   // 10 commits: (10-1)&1 = 1
    TCGEN05_FENCE_AFTER();

    // Epilogue: all 8 warps. tile = wid>>2, subpartition = wid&3.
    {
        const int tile = wid >> 2;
        const int srow = s0 + tile*128 + (wid & 3)*32 + lane;
        const float* sc2 = (const float*)(smem + SM_SC2);
        const float* scr = (const float*)(smem + SM_SCR);
        const float* sht = (const float*)(smem + SM_SHT);
        #pragma unroll
        for (int cb = 0; cb < 128; cb += 32) {
            uint32_t r1[32], r2[32];
            TCGEN05_LD_32X32B_X32(r1, tmem + tile*128 + cb);
            TCGEN05_LD_32X32B_X32(r2, tmem + 256 + tile*128 + cb);
            TCGEN05_WAIT_LD();
            #pragma unroll
            for (int j = 0; j < 32; ++j) {
                const int o = cb + j;
                const size_t base = ((size_t)(n*COUT + o)) * SLEN + srow;
                float v = fmaf(sc2[o], __uint_as_float(r1[j]),
                          fmaf(scr[o], __uint_as_float(r2[j]), sht[o]));
                out[base] = fmaxf(v, 0.f);
            }
        }
        TCGEN05_FENCE_BEFORE();
    }

    __syncthreads();
    if (tid == 0) MBARRIER_INVAL(sb + SM_MBAR);
    __syncthreads();
    if (wid == 0) TCGEN05_DEALLOC(tmem, 512);
#else
    // ------------------------- FFMA fallback: two 128-halves ---------------
    __syncthreads();
    const int tx = tid & 15, ty = tid >> 4;
    float* Zs = (float*)(smem + SM_A);
    float* Ws = (float*)(smem + SM_A + 16896);
    const float* sc2 = (const float*)(smem + SM_SC2);
    const float* scr = (const float*)(smem + SM_SCR);
    const float* sht = (const float*)(smem + SM_SHT);

    for (int half = 0; half < 2; ++half) {
        const int s0h = s0 + half*128;
        float acc[8][8], acc2[8][8];
        #pragma unroll
        for (int r = 0; r < 8; ++r)
            #pragma unroll
            for (int j = 0; j < 8; ++j) { acc[r][j] = 0.f; acc2[r][j] = 0.f; }

        for (int k = 0; k < 9; ++k) {
            const int sbase = s0h + 25*k - 100;
            for (int ic = 0; ic < 4; ++ic) {
                __syncthreads();
                for (int idx = tid; idx < 4096; idx += 256) {
                    const int row = idx >> 5, i = idx & 31;
                    const int gi = ic*32 + i;
                    const int sg = sbase + row;
                    float z = 0.f;
                    if ((unsigned)sg < (unsigned)SLEN)
                        z = __bfloat162float(zh[(size_t)sg*COUT + gi])
                          + __bfloat162float(zl[(size_t)sg*COUT + gi]);
                    Zs[i*132 + row] = z;
                    const size_t wb = ((size_t)k*COUT + row)*COUT + gi;
                    Ws[i*132 + row] = __bfloat162float(g_whi[wb]) + __bfloat162float(g_wlo[wb]);
                }
                __syncthreads();
                for (int i = 0; i < 32; ++i) {
                    float zr[8], wv[8];
                    #pragma unroll
                    for (int j = 0; j < 8; ++j) zr[j] = Zs[i*132 + tx*8 + j];
                    #pragma unroll
                    for (int r = 0; r < 8; ++r) wv[r] = Ws[i*132 + ty*8 + r];
                    #pragma unroll
                    for (int r = 0; r < 8; ++r)
                        #pragma unroll
                        for (int j = 0; j < 8; ++j)
                            acc[r][j] = fmaf(wv[r], zr[j], acc[r][j]);
                }
            }
        }
        for (int ic = 0; ic < 2; ++ic) {
            __syncthreads();
            for (int idx = tid; idx < 4096; idx += 256) {
                const int row = idx >> 5, i = idx & 31;
                const int gi = ic*32 + i;
                const size_t xb = ((size_t)(n*SLEN) + s0h + row)*CIN + gi;
                Zs[i*132 + row] = __bfloat162float(g_xthi[xb]) + __bfloat162float(g_xtlo[xb]);
                Ws[i*132 + row] = __bfloat162float(g_wrhi[row*CIN + gi])
                                + __bfloat162float(g_wrlo[row*CIN + gi]);
            }
            __syncthreads();
            for (int i = 0; i < 32; ++i) {
                float zr[8], wv[8];
                #pragma unroll
                for (int j = 0; j < 8; ++j) zr[j] = Zs[i*132 + tx*8 + j];
                #pragma unroll
                for (int r = 0; r < 8; ++r) wv[r] = Ws[i*132 + ty*8 + r];
                #pragma unroll
                for (int r = 0; r < 8; ++r)
                    #pragma unroll
                    for (int j = 0; j < 8; ++j)
                        acc2[r][j] = fmaf(wv[r], zr[j], acc2[r][j]);
            }
        }
        #pragma unroll
        for (int r = 0; r < 8; ++r) {
            const int o = ty*8 + r;
            const size_t base = ((size_t)(n*COUT + o))*SLEN + s0h + tx*8;
            #pragma unroll
            for (int j = 0; j < 8; ++j) {
                float v = fmaf(sc2[o], acc[r][j], fmaf(scr[o], acc2[r][j], sht[o]));
                out[base + j] = fmaxf(v, 0.f);
            }
        }
        __syncthreads();
    }
#endif
}

// ---------------------------------------------------------------------------
extern "C" void kernel_launch(void* const* d_in, const int* in_sizes, int n_in,
                              void* d_out, int out_size)
{
    const float* x     = (const float*)d_in[0];
    const float* Amat  = (const float*)d_in[1];
    const float* w2    = (const float*)d_in[4];
    const float* b2    = (const float*)d_in[5];
    const float* w3    = (const float*)d_in[6];
    const float* b3    = (const float*)d_in[7];
    const float* w4    = (const float*)d_in[8];
    const float* b4    = (const float*)d_in[9];
    const float* bn1_g = (const float*)d_in[10];
    const float* bn1_b = (const float*)d_in[11];
    const float* bn1_m = (const float*)d_in[12];
    const float* bn1_v = (const float*)d_in[13];
    const float* wt    = (const float*)d_in[14];
    const float* bt    = (const float*)d_in[15];
    const float* bn2_g = (const float*)d_in[16];
    const float* bn2_b = (const float*)d_in[17];
    const float* bn2_m = (const float*)d_in[18];
    const float* bn2_v = (const float*)d_in[19];
    const float* wr    = (const float*)d_in[20];
    const float* br    = (const float*)d_in[21];
    const float* bnr_g = (const float*)d_in[22];
    const float* bnr_b = (const float*)d_in[23];
    const float* bnr_m = (const float*)d_in[24];
    const float* bnr_v = (const float*)d_in[25];
    float* out = (float*)d_out;

    cudaFuncSetAttribute(kernelC, cudaFuncAttributeMaxDynamicSharedMemorySize,
                         SMEM_C_TOTAL);
    cudaFuncSetAttribute(kernelP, cudaFuncAttributeMaxDynamicSharedMemorySize,
                         SMEM_P_TOTAL);

    kernelW<<<(9*COUT*COUT + 255)/256, 256>>>(wt);
    kernelW2<<<(COUT*CIN + 255)/256, 256>>>(wr, w3, w4);
    kernelBX<<<dim3(SLEN/100, NB), 256>>>(x);
    kernelA0<<<(NB*CIN*VV + 255)/256, 256>>>();
    kernelA1<<<dim3(8, NB), 256>>>(x);
    kernelA2<<<NB, 256>>>(w2, b2);
    kernelP<<<dim3(NSTILE2, NB), 256, SMEM_P_TOTAL>>>();
    kernelZ<<<dim3(TT, NB), 128>>>(Amat, b3, b4,
                                   bn1_g, bn1_b, bn1_m, bn1_v);
    kernelC<<<dim3(NSTILE2, NB), 256, SMEM_C_TOTAL>>>(bt, bn2_g, bn2_b,
                                                      bn2_m, bn2_v,
                                                      br, bnr_g, bnr_b,
                                                      bnr_m, bnr_v, out);
}

// round 16
// speedup vs baseline: 1.1242x; 1.1242x over previous
#include <cuda_runtime.h>
#include <cuda_bf16.h>
#include <math.h>
#include <stdint.h>

// Problem constants
#define NB   32
#define CIN  64
#define COUT 128
#define TT   256
#define VV   25
#define IC   32
#define SLEN (TT*VV)          // 6400 flattened (t,v)
#define EPS  1e-5f
#define STILE 128
#define NSTILE (SLEN/STILE)   // 50  (kernelP tiling)
#define STILE2 256
#define NSTILE2 (SLEN/STILE2) // 25  (kernelC tiling)

#if defined(__CUDA_ARCH__) && (defined(__CUDA_ARCH_FEAT_SM103_ALL) || defined(__CUDA_ARCH_FEAT_SM100_ALL))
#define HAS_TC 1
#else
#define HAS_TC 0
#endif

// ---------------------------------------------------------------------------
// Device scratch (no allocation allowed). 16B-aligned for uint4 access.
// ---------------------------------------------------------------------------
__device__ __align__(16) __nv_bfloat16 g_zhi[(size_t)NB*SLEN*COUT];   // z^T [n][s][o]
__device__ __align__(16) __nv_bfloat16 g_zlo[(size_t)NB*SLEN*COUT];
__device__ __align__(16) __nv_bfloat16 g_xthi[(size_t)NB*SLEN*CIN];  // x^T [n][s][c]
__device__ __align__(16) __nv_bfloat16 g_xtlo[(size_t)NB*SLEN*CIN];
__device__ __align__(16) float g_x3[(size_t)NB*SLEN*COUT];           // w3@x fp32
__device__ __align__(16) float g_x4[(size_t)NB*SLEN*COUT];           // w4@x fp32
__device__ __align__(16) __nv_bfloat16 g_whi[9*COUT*COUT];            // wt [k][o][i]
__device__ __align__(16) __nv_bfloat16 g_wlo[9*COUT*COUT];
__device__ __align__(16) __nv_bfloat16 g_wrhi[COUT*CIN];              // wr [o][c]
__device__ __align__(16) __nv_bfloat16 g_wrlo[COUT*CIN];
__device__ __align__(16) __nv_bfloat16 g_w3hi[COUT*CIN];              // w3 [o][c]
__device__ __align__(16) __nv_bfloat16 g_w3lo[COUT*CIN];
__device__ __align__(16) __nv_bfloat16 g_w4hi[COUT*CIN];              // w4 [o][c]
__device__ __align__(16) __nv_bfloat16 g_w4lo[COUT*CIN];
__device__ __align__(16) float g_s[NB*IC*VV];                         // softmax weights
__device__ __align__(16) float g_xbar[NB*CIN*VV];                     // T-mean accum

// ---------------------------------------------------------------------------
// PTX helpers
// ---------------------------------------------------------------------------
__device__ __forceinline__ uint32_t smem_u32(const void* p) {
    uint32_t a;
    asm("{ .reg .u64 t; cvta.to.shared.u64 t, %1; cvt.u32.u64 %0, t; }"
        : "=r"(a) : "l"(p));
    return a;
}

#if HAS_TC
__device__ __forceinline__ uint32_t elect_one_pred() {
    uint32_t pred;
    asm volatile("{\n\t.reg .pred p;\n\telect.sync _|p, 0xFFFFFFFF;\n\t"
                 "selp.b32 %0, 1, 0, p;\n\t}" : "=r"(pred));
    return pred;
}
#define TCGEN05_ALLOC(smem_addr, nCols) \
    asm volatile("tcgen05.alloc.cta_group::1.sync.aligned.shared::cta.b32 [%0], %1;" \
        :: "r"((uint32_t)(smem_addr)), "r"((uint32_t)(nCols)) : "memory")
#define TCGEN05_DEALLOC(tmem_addr, nCols) \
    asm volatile("tcgen05.dealloc.cta_group::1.sync.aligned.b32 %0, %1;" \
        :: "r"(tmem_addr), "r"((uint32_t)(nCols)))
#define TCGEN05_COMMIT(mbar) \
    asm volatile("tcgen05.commit.cta_group::1.mbarrier::arrive::one.shared::cluster.b64 [%0];" \
        :: "r"((uint32_t)(mbar)) : "memory")
#define TCGEN05_FENCE_AFTER() \
    asm volatile("tcgen05.fence::after_thread_sync;" ::: "memory")
#define TCGEN05_FENCE_BEFORE() \
    asm volatile("tcgen05.fence::before_thread_sync;" ::: "memory")
#define TCGEN05_WAIT_LD() \
    asm volatile("tcgen05.wait::ld.sync.aligned;" ::: "memory")
#define FENCE_PROXY_ASYNC() \
    asm volatile("fence.proxy.async.shared::cta;" ::: "memory")
#define MBARRIER_INIT(mbar, cnt) \
    asm volatile("mbarrier.init.shared.b64 [%0], %1;" \
        :: "r"((uint32_t)(mbar)), "r"((uint32_t)(cnt)) : "memory")
#define MBARRIER_INVAL(mbar) \
    asm volatile("mbarrier.inval.shared.b64 [%0];" :: "r"((uint32_t)(mbar)) : "memory")
#define MBARRIER_WAIT_PARITY(mbar, phase) do { \
    uint32_t _m = (uint32_t)(mbar); uint32_t _p = (uint32_t)(phase); uint32_t _d; \
    asm volatile("{\n\t.reg .pred p;\n\t" \
        "mbarrier.try_wait.parity.acquire.cta.shared::cta.b64 p, [%1], %2;\n\t" \
        "selp.b32 %0, 1, 0, p;\n\t}" : "=r"(_d) : "r"(_m), "r"(_p) : "memory"); \
    if (!_d) { \
        asm volatile("{\n\t.reg .pred P1;\n\t" \
            "WAIT_LOOP_%=:\n\t" \
            "mbarrier.try_wait.parity.acquire.cta.shared::cta.b64 P1, [%0], %1, 0x989680;\n\t" \
            "@P1 bra.uni WAIT_DONE_%=;\n\t" \
            "bra.uni WAIT_LOOP_%=;\n\t" \
            "WAIT_DONE_%=:\n\t}" :: "r"(_m), "r"(_p) : "memory"); \
    } \
} while (0)
#define TCGEN05_LD_32X32B_X32(r, tmem_addr) \
    asm volatile("tcgen05.ld.sync.aligned.32x32b.x32.b32 " \
        "{%0, %1, %2, %3, %4, %5, %6, %7, " \
        " %8, %9, %10, %11, %12, %13, %14, %15, " \
        " %16, %17, %18, %19, %20, %21, %22, %23, " \
        " %24, %25, %26, %27, %28, %29, %30, %31}, [%32];" \
        : "=r"((r)[0]),  "=r"((r)[1]),  "=r"((r)[2]),  "=r"((r)[3]), \
          "=r"((r)[4]),  "=r"((r)[5]),  "=r"((r)[6]),  "=r"((r)[7]), \
          "=r"((r)[8]),  "=r"((r)[9]),  "=r"((r)[10]), "=r"((r)[11]), \
          "=r"((r)[12]), "=r"((r)[13]), "=r"((r)[14]), "=r"((r)[15]), \
          "=r"((r)[16]), "=r"((r)[17]), "=r"((r)[18]), "=r"((r)[19]), \
          "=r"((r)[20]), "=r"((r)[21]), "=r"((r)[22]), "=r"((r)[23]), \
          "=r"((r)[24]), "=r"((r)[25]), "=r"((r)[26]), "=r"((r)[27]), \
          "=r"((r)[28]), "=r"((r)[29]), "=r"((r)[30]), "=r"((r)[31]) \
        : "r"(tmem_addr))

static constexpr uint64_t DESC_BASE_SW128 =
    (uint64_t(2) << 61) | (uint64_t(1) << 46) | (uint64_t(64) << 32) | (uint64_t(1) << 16);
__device__ __forceinline__ uint64_t make_desc(uint32_t addr) {
    return DESC_BASE_SW128 | ((uint64_t)(addr >> 4) & 0x3FFF);
}
#define MMA_IDESC 0x8200490u

__device__ __forceinline__ void mma_f16_ss(uint32_t d, uint64_t ad, uint64_t bd,
                                           uint32_t idesc, bool en) {
    uint32_t e = en ? 1u : 0u, z = 0u;
    asm volatile("{\n\t.reg .pred p;\n\tsetp.ne.u32 p, %5, 0;\n\t"
        "tcgen05.mma.cta_group::1.kind::f16 [%0], %1, %2, %3, {%4, %4, %4, %4}, p;\n\t}"
        :: "r"(d), "l"(ad), "l"(bd), "r"(idesc), "r"(z), "r"(e) : "memory");
}
#endif  // HAS_TC

#define SWZ128(x) ((x) ^ (((x) >> 3) & 0x70))

// ---------------------------------------------------------------------------
// Prep kernels: weight bf16 hi/lo splits
// ---------------------------------------------------------------------------
__global__ void kernelW(const float* __restrict__ wt)
{
    int idx = blockIdx.x * 256 + threadIdx.x;
    if (idx >= 9*COUT*COUT) return;
    int k = idx / (COUT*COUT);
    int r = idx % (COUT*COUT);
    int o = r / COUT, i = r % COUT;
    float w = wt[((size_t)o*COUT + i)*9 + k];
    __nv_bfloat16 h = __float2bfloat16(w);
    g_whi[idx] = h;
    g_wlo[idx] = __float2bfloat16(w - __bfloat162float(h));
}

__global__ void kernelW2(const float* __restrict__ wr,
                         const float* __restrict__ w3,
                         const float* __restrict__ w4)
{
    int idx = blockIdx.x * 256 + threadIdx.x;
    if (idx >= COUT*CIN) return;
    float w = wr[idx];
    __nv_bfloat16 h = __float2bfloat16(w);
    g_wrhi[idx] = h; g_wrlo[idx] = __float2bfloat16(w - __bfloat162float(h));
    w = w3[idx]; h = __float2bfloat16(w);
    g_w3hi[idx] = h; g_w3lo[idx] = __float2bfloat16(w - __bfloat162float(h));
    w = w4[idx]; h = __float2bfloat16(w);
    g_w4hi[idx] = h; g_w4lo[idx] = __float2bfloat16(w - __bfloat162float(h));
}

// ---------------------------------------------------------------------------
// Kernel BX: transpose x -> xT[n][s][c] bf16 hi/lo
// ---------------------------------------------------------------------------
__global__ void __launch_bounds__(256) kernelBX(const float* __restrict__ x)
{
    __shared__ float xs[CIN*101];
    const int n  = blockIdx.y;
    const int s0 = blockIdx.x * 100;
    const int tid = threadIdx.x;

    for (int idx = tid; idx < CIN*100; idx += 256) {
        const int c = idx / 100, j = idx % 100;
        xs[c*101 + j] = x[((size_t)(n*CIN + c))*SLEN + s0 + j];
    }
    __syncthreads();
    for (int idx = tid; idx < CIN*100; idx += 256) {
        const int j = idx / CIN, c = idx % CIN;
        const float v = xs[c*101 + j];
        const __nv_bfloat16 h = __float2bfloat16(v);
        const size_t base = ((size_t)(n*SLEN + s0 + j))*CIN + c;
        g_xthi[base] = h;
        g_xtlo[base] = __float2bfloat16(v - __bfloat162float(h));
    }
}

// ---------------------------------------------------------------------------
// Kernel A split: A0 zero, A1 partial T-mean via atomicAdd, A2 softmax
// ---------------------------------------------------------------------------
__global__ void kernelA0()
{
    int idx = blockIdx.x * 256 + threadIdx.x;
    if (idx < NB*CIN*VV) g_xbar[idx] = 0.f;
}

__global__ void kernelA1(const float* __restrict__ x)
{
    const int n = blockIdx.y;
    const int tbase = blockIdx.x * (TT/8);
    const int tid = threadIdx.x;
    for (int idx = tid; idx < CIN*VV; idx += 256) {
        int c = idx / VV, v = idx % VV;
        const float* xp = x + (((size_t)(n*CIN + c)*TT) + tbase)*VV + v;
        float sum = 0.f;
        #pragma unroll 8
        for (int t = 0; t < TT/8; ++t) sum += xp[t*VV];
        atomicAdd(&g_xbar[n*CIN*VV + idx], sum * (1.0f/256.0f));
    }
}

__global__ void kernelA2(const float* __restrict__ w2,
                         const float* __restrict__ b2)
{
    const int n = blockIdx.x;
    const int tid = threadIdx.x;
    __shared__ float xbar[CIN*VV];
    __shared__ float x2s[IC*VV];

    for (int idx = tid; idx < CIN*VV; idx += 256)
        xbar[idx] = g_xbar[n*CIN*VV + idx];
    __syncthreads();
    for (int idx = tid; idx < IC*VV; idx += 256) {
        int i = idx / VV, v = idx % VV;
        float acc = b2[i];
        for (int c = 0; c < CIN; ++c)
            acc = fmaf(w2[i*CIN + c], xbar[c*VV + v], acc);
        x2s[idx] = acc;
    }
    __syncthreads();
    if (tid < IC) {
        const int i = tid;
        float mx = -1e30f;
        #pragma unroll
        for (int v = 0; v < VV; ++v) mx = fmaxf(mx, -x2s[i*VV + v]);
        float e[VV]; float sum = 0.f;
        #pragma unroll
        for (int v = 0; v < VV; ++v) { e[v] = expf(-x2s[i*VV + v] - mx); sum += e[v]; }
        float inv = 1.0f / sum;
        #pragma unroll
        for (int v = 0; v < VV; ++v) g_s[(n*IC + i)*VV + v] = e[v] * inv;
    }
}

// ---------------------------------------------------------------------------
// Kernel P (R14 structure): tcgen05 dual GEMM x3 = w3@xT, x4 = w4@xT (K=64)
// Epilogue writes fp32 directly.
// ---------------------------------------------------------------------------
#define P_TMEM   0
#define P_MBAR   8
#define P_X_HI   1024
#define P_X_LO   (P_X_HI + 16384)
#define P_W3_HI  (P_X_LO + 16384)
#define P_W3_LO  (P_W3_HI + 16384)
#define P_W4_HI  (P_W3_LO + 16384)
#define P_W4_LO  (P_W4_HI + 16384)
#define SMEM_P_TOTAL (P_W4_LO + 16384)   // 99328

__global__ void __launch_bounds__(256) kernelP()
{
    extern __shared__ char smem[];
    const int n  = blockIdx.y;
    const int s0 = blockIdx.x * STILE;
    const int tid = threadIdx.x;

#if HAS_TC
    const uint32_t sb = smem_u32(smem);
    const int wid = tid >> 5;
    const int lane = tid & 31;

    if (wid == 0) { TCGEN05_ALLOC(sb + P_TMEM, 256); }
    if (tid == 0) MBARRIER_INIT(sb + P_MBAR, 1);
    __syncthreads();
    uint32_t tmem;
    asm volatile("ld.shared.b32 %0, [%1];" : "=r"(tmem) : "r"(sb + P_TMEM));

    for (int idx = tid; idx < 1024; idx += 256) {
        const int row = idx >> 3, c8 = idx & 7;
        const uint32_t so = SWZ128((row << 7) + (c8 << 4));
        const size_t xb = ((size_t)(n*SLEN) + s0 + row)*CIN;
        *(uint4*)(smem + P_X_HI + so)  = *((const uint4*)(g_xthi + xb) + c8);
        *(uint4*)(smem + P_X_LO + so)  = *((const uint4*)(g_xtlo + xb) + c8);
        *(uint4*)(smem + P_W3_HI + so) = *((const uint4*)(g_w3hi + (size_t)row*CIN) + c8);
        *(uint4*)(smem + P_W3_LO + so) = *((const uint4*)(g_w3lo + (size_t)row*CIN) + c8);
        *(uint4*)(smem + P_W4_HI + so) = *((const uint4*)(g_w4hi + (size_t)row*CIN) + c8);
        *(uint4*)(smem + P_W4_LO + so) = *((const uint4*)(g_w4lo + (size_t)row*CIN) + c8);
    }
    FENCE_PROXY_ASYNC();
    __syncthreads();

    if (wid == 0) {
        TCGEN05_FENCE_AFTER();
        if (elect_one_pred()) {
            const uint32_t XO[3] = { P_X_HI, P_X_LO, P_X_HI };
            #pragma unroll
            for (int dsel = 0; dsel < 2; ++dsel) {
                const uint32_t WH = dsel ? P_W4_HI : P_W3_HI;
                const uint32_t WL = dsel ? P_W4_LO : P_W3_LO;
                const uint32_t WO[3] = { WH, WH, WL };
                const uint32_t d = tmem + dsel*128;
                #pragma unroll
                for (int c3 = 0; c3 < 3; ++c3) {
                    uint64_t ad = make_desc(sb + XO[c3]);
                    uint64_t bd = make_desc(sb + WO[c3]);
                    #pragma unroll
                    for (int ks = 0; ks < 4; ++ks) {
                        const bool en = !(c3 == 0 && ks == 0);
                        mma_f16_ss(d, ad + ks*2, bd + ks*2, MMA_IDESC, en);
                    }
                }
            }
            TCGEN05_COMMIT(sb + P_MBAR);
        }
    }

    MBARRIER_WAIT_PARITY(sb + P_MBAR, 0);
    TCGEN05_FENCE_AFTER();

    if (wid < 4) {
        const int srow = s0 + wid * 32 + lane;
        const size_t base = ((size_t)(n*SLEN) + srow)*COUT;
        #pragma unroll
        for (int cb = 0; cb < 128; cb += 32) {
            uint32_t r1[32], r2[32];
            TCGEN05_LD_32X32B_X32(r1, tmem + cb);
            TCGEN05_LD_32X32B_X32(r2, tmem + 128 + cb);
            TCGEN05_WAIT_LD();
            #pragma unroll
            for (int j = 0; j < 32; ++j) {
                g_x3[base + cb + j] = __uint_as_float(r1[j]);
                g_x4[base + cb + j] = __uint_as_float(r2[j]);
            }
        }
        TCGEN05_FENCE_BEFORE();
    }

    __syncthreads();
    if (tid == 0) MBARRIER_INVAL(sb + P_MBAR);
    __syncthreads();
    if (wid == 0) TCGEN05_DEALLOC(tmem, 256);
#else
    __syncthreads();
    const int tx = tid & 15, ty = tid >> 4;
    float* Xs = (float*)(smem + P_X_HI);
    float* Ws = (float*)(smem + P_X_HI + 16896);
    for (int dsel = 0; dsel < 2; ++dsel) {
        float acc[8][8];
        #pragma unroll
        for (int r = 0; r < 8; ++r)
            #pragma unroll
            for (int j = 0; j < 8; ++j) acc[r][j] = 0.f;
        for (int ic = 0; ic < 2; ++ic) {
            __syncthreads();
            for (int idx = tid; idx < 4096; idx += 256) {
                const int row = idx >> 5, i = idx & 31;
                const int gi = ic*32 + i;
                const size_t xb = ((size_t)(n*SLEN) + s0 + row)*CIN + gi;
                Xs[i*132 + row] = __bfloat162float(g_xthi[xb]) + __bfloat162float(g_xtlo[xb]);
                const __nv_bfloat16* whp = dsel ? g_w4hi : g_w3hi;
                const __nv_bfloat16* wlp = dsel ? g_w4lo : g_w3lo;
                Ws[i*132 + row] = __bfloat162float(whp[row*CIN + gi])
                                + __bfloat162float(wlp[row*CIN + gi]);
            }
            __syncthreads();
            for (int i = 0; i < 32; ++i) {
                float zr[8], wv[8];
                #pragma unroll
                for (int j = 0; j < 8; ++j) zr[j] = Xs[i*132 + tx*8 + j];
                #pragma unroll
                for (int r = 0; r < 8; ++r) wv[r] = Ws[i*132 + ty*8 + r];
                #pragma unroll
                for (int r = 0; r < 8; ++r)
                    #pragma unroll
                    for (int j = 0; j < 8; ++j)
                        acc[r][j] = fmaf(wv[r], zr[j], acc[r][j]);
            }
        }
        float* dd = dsel ? g_x4 : g_x3;
        #pragma unroll
        for (int r = 0; r < 8; ++r) {
            const int o = ty*8 + r;
            #pragma unroll
            for (int j = 0; j < 8; ++j) {
                const int srow = s0 + tx*8 + j;
                dd[((size_t)(n*SLEN) + srow)*COUT + o] = acc[r][j];
            }
        }
        __syncthreads();
    }
#endif
}

// ---------------------------------------------------------------------------
// Kernel Z: z = relu(bn1(g + A@(x4+b4))) from fp32 x3/x4. grid (TT, NB).
// ---------------------------------------------------------------------------
__global__ void __launch_bounds__(128) kernelZ(
    const float* __restrict__ Amat,
    const float* __restrict__ b3, const float* __restrict__ b4,
    const float* __restrict__ bn1_g, const float* __restrict__ bn1_b,
    const float* __restrict__ bn1_m, const float* __restrict__ bn1_v)
{
    const int n = blockIdx.y;
    const int t = blockIdx.x;
    const int o = threadIdx.x;
    const int c32 = o & 31;

    __shared__ float As[VV*VV];
    __shared__ float ss[IC*VV];
    for (int idx = o; idx < VV*VV; idx += 128) As[idx] = Amat[idx];
    for (int idx = o; idx < IC*VV; idx += 128) ss[idx] = g_s[n*IC*VV + idx];
    __syncthreads();

    const float scale1 = bn1_g[o] * rsqrtf(bn1_v[o] + EPS);
    const float shift1 = bn1_b[o] - bn1_m[o] * scale1;
    const float b3o = b3[o], b4o = b4[o];

    const size_t base = ((size_t)(n*SLEN) + t*VV)*COUT + o;
    float x3v[VV], x4v[VV];
    #pragma unroll
    for (int v = 0; v < VV; ++v) {
        const size_t a = base + (size_t)v*COUT;
        x3v[v] = g_x3[a];
        x4v[v] = g_x4[a] + b4o;
    }

    float g = b3o;
    const float* srow = &ss[c32*VV];
    #pragma unroll
    for (int v = 0; v < VV; ++v) g = fmaf(srow[v], x3v[v], g);

    #pragma unroll
    for (int u = 0; u < VV; ++u) {
        float y2 = 0.f;
        const float* arow = &As[u*VV];
        #pragma unroll
        for (int v = 0; v < VV; ++v) y2 = fmaf(arow[v], x4v[v], y2);
        float z = fmaxf(fmaf(scale1, g + y2, shift1), 0.f);
        __nv_bfloat16 zh = __float2bfloat16(z);
        const size_t a = base + (size_t)u*COUT;
        g_zhi[a] = zh;
        g_zlo[a] = __float2bfloat16(z - __bfloat162float(zh));
    }
}

// ---------------------------------------------------------------------------
// Kernel C (R14-exact): dual s-tile, register-prefetched A halo only.
// ---------------------------------------------------------------------------
#define SM_TMEM   0
#define SM_MBAR   8
#define SM_SC2    16
#define SM_SCR    528
#define SM_SHT    1040
#define SM_A      2048                   // hi: p0@0 p1@32768 ; lo: +65536
#define SM_B      (SM_A + 131072)        // hi p0@0 p1@16384 ; lo +32768
#define SMEM_C_TOTAL (SM_B + 65536)      // 198656

__global__ void __launch_bounds__(256) kernelC(
    const float* __restrict__ bt,
    const float* __restrict__ bn2_g, const float* __restrict__ bn2_b,
    const float* __restrict__ bn2_m, const float* __restrict__ bn2_v,
    const float* __restrict__ br,
    const float* __restrict__ bnr_g, const float* __restrict__ bnr_b,
    const float* __restrict__ bnr_m, const float* __restrict__ bnr_v,
    float* __restrict__ out)
{
    extern __shared__ char smem[];
    const int n  = blockIdx.y;
    const int s0 = blockIdx.x * STILE2;
    const int tid = threadIdx.x;

    if (tid < COUT) {
        float sc2 = bn2_g[tid] * rsqrtf(bn2_v[tid] + EPS);
        float sh2 = bn2_b[tid] - bn2_m[tid] * sc2;
        float scr = bnr_g[tid] * rsqrtf(bnr_v[tid] + EPS);
        float shr = bnr_b[tid] - bnr_m[tid] * scr;
        ((float*)(smem + SM_SC2))[tid] = sc2;
        ((float*)(smem + SM_SCR))[tid] = scr;
        ((float*)(smem + SM_SHT))[tid] = fmaf(sc2, bt[tid], sh2) + fmaf(scr, br[tid], shr);
    }

    const __nv_bfloat16* zh = g_zhi + (size_t)n * SLEN * COUT;
    const __nv_bfloat16* zl = g_zlo + (size_t)n * SLEN * COUT;

#if HAS_TC
    const uint32_t sb = smem_u32(smem);
    const int wid = tid >> 5;
    const int lane = tid & 31;

    if (wid == 0) { TCGEN05_ALLOC(sb + SM_TMEM, 512); }
    if (tid == 0) MBARRIER_INIT(sb + SM_MBAR, 1);
    __syncthreads();
    uint32_t tmem;
    asm volatile("ld.shared.b32 %0, [%1];" : "=r"(tmem) : "r"(sb + SM_TMEM));

    // ---- stage 0: res GEMM ----
    for (int idx = tid; idx < 2048; idx += 256) {
        const int row = idx >> 3, c8 = idx & 7;
        const uint32_t so = SWZ128((row << 7) + (c8 << 4));
        const size_t xb = ((size_t)(n*SLEN) + s0 + row)*CIN;
        *(uint4*)(smem + SM_A + so)          = *((const uint4*)(g_xthi + xb) + c8);
        *(uint4*)(smem + SM_A + 65536 + so)  = *((const uint4*)(g_xtlo + xb) + c8);
    }
    for (int idx = tid; idx < 1024; idx += 256) {
        const int row = idx >> 3, c8 = idx & 7;
        const uint32_t so = SWZ128((row << 7) + (c8 << 4));
        *(uint4*)(smem + SM_B + so)         = *((const uint4*)(g_wrhi + (size_t)row*CIN) + c8);
        *(uint4*)(smem + SM_B + 32768 + so) = *((const uint4*)(g_wrlo + (size_t)row*CIN) + c8);
    }
    FENCE_PROXY_ASYNC();
    __syncthreads();

    if (wid == 0) {
        TCGEN05_FENCE_AFTER();
        if (elect_one_pred()) {
            #pragma unroll
            for (int tile = 0; tile < 2; ++tile) {
                const uint32_t d = tmem + 256 + tile*128;
                const uint32_t XO[3] = { 0u, 65536u, 0u };
                const uint32_t WO[3] = { 0u, 0u, 32768u };
                #pragma unroll
                for (int c3 = 0; c3 < 3; ++c3) {
                    uint64_t ad = make_desc(sb + SM_A + XO[c3] + tile*16384);
                    uint64_t bd = make_desc(sb + SM_B + WO[c3]);
                    #pragma unroll
                    for (int ks = 0; ks < 4; ++ks) {
                        const bool en = !(c3 == 0 && ks == 0);
                        mma_f16_ss(d, ad + ks*2, bd + ks*2, MMA_IDESC, en);
                    }
                }
            }
            TCGEN05_COMMIT(sb + SM_MBAR);
        }
    }

    // ---- prefetch A halo for tap 0 into registers ----
    uint4 pah[16], pal[16];
    {
        const int sbase = s0 - 100;
        #pragma unroll
        for (int j = 0; j < 16; ++j) {
            const int idx = tid + 256*j;
            const int row = idx >> 4, c = idx & 15;
            const int sg = sbase + row;
            uint4 vh = make_uint4(0,0,0,0), vl = make_uint4(0,0,0,0);
            if ((unsigned)sg < (unsigned)SLEN) {
                vh = *((const uint4*)(zh + (size_t)sg * COUT) + c);
                vl = *((const uint4*)(zl + (size_t)sg * COUT) + c);
            }
            pah[j] = vh; pal[j] = vl;
        }
    }

    // ---- conv stages ----
    for (int st = 1; st <= 9; ++st) {
        const int k = st - 1;
        MBARRIER_WAIT_PARITY(sb + SM_MBAR, (st - 1) & 1);

        // store prefetched A halo
        #pragma unroll
        for (int j = 0; j < 16; ++j) {
            const int idx = tid + 256*j;
            const int row = idx >> 4, c = idx & 15;
            const uint32_t so = ((c >> 3) << 15) + SWZ128((row << 7) + ((c & 7) << 4));
            *(uint4*)(smem + SM_A + so)         = pah[j];
            *(uint4*)(smem + SM_A + 65536 + so) = pal[j];
        }
        // B tap k (L2-resident weights, direct)
        const uint4* wh = (const uint4*)(g_whi + (size_t)k * COUT * COUT);
        const uint4* wl = (const uint4*)(g_wlo + (size_t)k * COUT * COUT);
        for (int idx = tid; idx < 2048; idx += 256) {
            const int row = idx >> 4, c = idx & 15;
            const uint32_t so = ((c >> 3) << 14) + SWZ128((row << 7) + ((c & 7) << 4));
            *(uint4*)(smem + SM_B + so)         = wh[idx];
            *(uint4*)(smem + SM_B + 32768 + so) = wl[idx];
        }
        FENCE_PROXY_ASYNC();
        __syncthreads();

        if (wid == 0) {
            TCGEN05_FENCE_AFTER();
            if (elect_one_pred()) {
                const uint32_t ALO[3] = { 0u, 65536u, 0u };
                const uint32_t BLO[3] = { 0u, 0u, 32768u };
                #pragma unroll
                for (int tile = 0; tile < 2; ++tile) {
                    const uint32_t d = tmem + tile*128;
                    #pragma unroll
                    for (int c3 = 0; c3 < 3; ++c3) {
                        #pragma unroll
                        for (int pl = 0; pl < 2; ++pl) {
                            uint64_t ad = make_desc(sb + SM_A + ALO[c3] + (pl << 15) + tile*16384);
                            uint64_t bd = make_desc(sb + SM_B + BLO[c3] + (pl << 14));
                            #pragma unroll
                            for (int ks = 0; ks < 4; ++ks) {
                                const bool en = !(st == 1 && c3 == 0 && pl == 0 && ks == 0);
                                mma_f16_ss(d, ad + ks*2, bd + ks*2, MMA_IDESC, en);
                            }
                        }
                    }
                }
                TCGEN05_COMMIT(sb + SM_MBAR);
            }
        }

        // prefetch next tap's A halo (gmem reads only; overlaps MMA)
        if (st < 9) {
            const int sbase = s0 + 25*st - 100;   // tap k+1 = st
            #pragma unroll
            for (int j = 0; j < 16; ++j) {
                const int idx = tid + 256*j;
                const int row = idx >> 4, c = idx & 15;
                const int sg = sbase + row;
                uint4 vh = make_uint4(0,0,0,0), vl = make_uint4(0,0,0,0);
                if ((unsigned)sg < (unsigned)SLEN) {
                    vh = *((const uint4*)(zh + (size_t)sg * COUT) + c);
                    vl = *((const uint4*)(zl + (size_t)sg * COUT) + c);
                }
                pah[j] = vh; pal[j] = vl;
            }
        }
    }

    MBARRIER_WAIT_PARITY(sb + SM_MBAR, 1);   // 10 commits: (10-1)&1 = 1
    TCGEN05_FENCE_AFTER();

    // Epilogue: all 8 warps. tile = wid>>2, subpartition = wid&3.
    {
        const int tile = wid >> 2;
        const int srow = s0 + tile*128 + (wid & 3)*32 + lane;
        const float* sc2 = (const float*)(smem + SM_SC2);
        const float* scr = (const float*)(smem + SM_SCR);
        const float* sht = (const float*)(smem + SM_SHT);
        #pragma unroll
        for (int cb = 0; cb < 128; cb += 32) {
            uint32_t r1[32], r2[32];
            TCGEN05_LD_32X32B_X32(r1, tmem + tile*128 + cb);
            TCGEN05_LD_32X32B_X32(r2, tmem + 256 + tile*128 + cb);
            TCGEN05_WAIT_LD();
            #pragma unroll
            for (int j = 0; j < 32; ++j) {
                const int o = cb + j;
                const size_t base = ((size_t)(n*COUT + o)) * SLEN + srow;
                float v = fmaf(sc2[o], __uint_as_float(r1[j]),
                          fmaf(scr[o], __uint_as_float(r2[j]), sht[o]));
                out[base] = fmaxf(v, 0.f);
            }
        }
        TCGEN05_FENCE_BEFORE();
    }

    __syncthreads();
    if (tid == 0) MBARRIER_INVAL(sb + SM_MBAR);
    __syncthreads();
    if (wid == 0) TCGEN05_DEALLOC(tmem, 512);
#else
    // ------------------------- FFMA fallback: two 128-halves ---------------
    __syncthreads();
    const int tx = tid & 15, ty = tid >> 4;
    float* Zs = (float*)(smem + SM_A);
    float* Ws = (float*)(smem + SM_A + 16896);
    const float* sc2 = (const float*)(smem + SM_SC2);
    const float* scr = (const float*)(smem + SM_SCR);
    const float* sht = (const float*)(smem + SM_SHT);

    for (int half = 0; half < 2; ++half) {
        const int s0h = s0 + half*128;
        float acc[8][8], acc2[8][8];
        #pragma unroll
        for (int r = 0; r < 8; ++r)
            #pragma unroll
            for (int j = 0; j < 8; ++j) { acc[r][j] = 0.f; acc2[r][j] = 0.f; }

        for (int k = 0; k < 9; ++k) {
            const int sbase = s0h + 25*k - 100;
            for (int ic = 0; ic < 4; ++ic) {
                __syncthreads();
                for (int idx = tid; idx < 4096; idx += 256) {
                    const int row = idx >> 5, i = idx & 31;
                    const int gi = ic*32 + i;
                    const int sg = sbase + row;
                    float z = 0.f;
                    if ((unsigned)sg < (unsigned)SLEN)
                        z = __bfloat162float(zh[(size_t)sg*COUT + gi])
                          + __bfloat162float(zl[(size_t)sg*COUT + gi]);
                    Zs[i*132 + row] = z;
                    const size_t wb = ((size_t)k*COUT + row)*COUT + gi;
                    Ws[i*132 + row] = __bfloat162float(g_whi[wb]) + __bfloat162float(g_wlo[wb]);
                }
                __syncthreads();
                for (int i = 0; i < 32; ++i) {
                    float zr[8], wv[8];
                    #pragma unroll
                    for (int j = 0; j < 8; ++j) zr[j] = Zs[i*132 + tx*8 + j];
                    #pragma unroll
                    for (int r = 0; r < 8; ++r) wv[r] = Ws[i*132 + ty*8 + r];
                    #pragma unroll
                    for (int r = 0; r < 8; ++r)
                        #pragma unroll
                        for (int j = 0; j < 8; ++j)
                            acc[r][j] = fmaf(wv[r], zr[j], acc[r][j]);
                }
            }
        }
        for (int ic = 0; ic < 2; ++ic) {
            __syncthreads();
            for (int idx = tid; idx < 4096; idx += 256) {
                const int row = idx >> 5, i = idx & 31;
                const int gi = ic*32 + i;
                const size_t xb = ((size_t)(n*SLEN) + s0h + row)*CIN + gi;
                Zs[i*132 + row] = __bfloat162float(g_xthi[xb]) + __bfloat162float(g_xtlo[xb]);
                Ws[i*132 + row] = __bfloat162float(g_wrhi[row*CIN + gi])
                                + __bfloat162float(g_wrlo[row*CIN + gi]);
            }
            __syncthreads();
            for (int i = 0; i < 32; ++i) {
                float zr[8], wv[8];
                #pragma unroll
                for (int j = 0; j < 8; ++j) zr[j] = Zs[i*132 + tx*8 + j];
                #pragma unroll
                for (int r = 0; r < 8; ++r) wv[r] = Ws[i*132 + ty*8 + r];
                #pragma unroll
                for (int r = 0; r < 8; ++r)
                    #pragma unroll
                    for (int j = 0; j < 8; ++j)
                        acc2[r][j] = fmaf(wv[r], zr[j], acc2[r][j]);
            }
        }
        #pragma unroll
        for (int r = 0; r < 8; ++r) {
            const int o = ty*8 + r;
            const size_t base = ((size_t)(n*COUT + o))*SLEN + s0h + tx*8;
            #pragma unroll
            for (int j = 0; j < 8; ++j) {
                float v = fmaf(sc2[o], acc[r][j], fmaf(scr[o], acc2[r][j], sht[o]));
                out[base + j] = fmaxf(v, 0.f);
            }
        }
        __syncthreads();
    }
#endif
}

// ---------------------------------------------------------------------------
extern "C" void kernel_launch(void* const* d_in, const int* in_sizes, int n_in,
                              void* d_out, int out_size)
{
    const float* x     = (const float*)d_in[0];
    const float* Amat  = (const float*)d_in[1];
    const float* w2    = (const float*)d_in[4];
    const float* b2    = (const float*)d_in[5];
    const float* w3    = (const float*)d_in[6];
    const float* b3    = (const float*)d_in[7];
    const float* w4    = (const float*)d_in[8];
    const float* b4    = (const float*)d_in[9];
    const float* bn1_g = (const float*)d_in[10];
    const float* bn1_b = (const float*)d_in[11];
    const float* bn1_m = (const float*)d_in[12];
    const float* bn1_v = (const float*)d_in[13];
    const float* wt    = (const float*)d_in[14];
    const float* bt    = (const float*)d_in[15];
    const float* bn2_g = (const float*)d_in[16];
    const float* bn2_b = (const float*)d_in[17];
    const float* bn2_m = (const float*)d_in[18];
    const float* bn2_v = (const float*)d_in[19];
    const float* wr    = (const float*)d_in[20];
    const float* br    = (const float*)d_in[21];
    const float* bnr_g = (const float*)d_in[22];
    const float* bnr_b = (const float*)d_in[23];
    const float* bnr_m = (const float*)d_in[24];
    const float* bnr_v = (const float*)d_in[25];
    float* out = (float*)d_out;

    cudaFuncSetAttribute(kernelC, cudaFuncAttributeMaxDynamicSharedMemorySize,
                         SMEM_C_TOTAL);
    cudaFuncSetAttribute(kernelP, cudaFuncAttributeMaxDynamicSharedMemorySize,
                         SMEM_P_TOTAL);

    kernelW<<<(9*COUT*COUT + 255)/256, 256>>>(wt);
    kernelW2<<<(COUT*CIN + 255)/256, 256>>>(wr, w3, w4);
    kernelBX<<<dim3(SLEN/100, NB), 256>>>(x);
    kernelA0<<<(NB*CIN*VV + 255)/256, 256>>>();
    kernelA1<<<dim3(8, NB), 256>>>(x);
    kernelA2<<<NB, 256>>>(w2, b2);
    kernelP<<<dim3(NSTILE, NB), 256, SMEM_P_TOTAL>>>();
    kernelZ<<<dim3(TT, NB), 128>>>(Amat, b3, b4,
                                   bn1_g, bn1_b, bn1_m, bn1_v);
    kernelC<<<dim3(NSTILE2, NB), 256, SMEM_C_TOTAL>>>(bt, bn2_g, bn2_b,
                                                      bn2_m, bn2_v,
                                                      br, bnr_g, bnr_b,
                                                      bnr_m, bnr_v, out);
}